// round 1
// baseline (speedup 1.0000x reference)
#include <cuda_runtime.h>
#include <math_constants.h>

// Problem constants
#define B_    16
#define C_    256
#define HW_   1024
#define NTOK  16384      // B_*HW_
#define KCODE 8192

#define XQ_SIZE  4194304 // B_*C_*HW_
#define LOSS_OFF 4194304
#define CODE_OFF 4194305

// Scratch (device globals; no allocation allowed)
__device__ float  g_xT[NTOK * C_];     // token-major x
__device__ float  g_hn[KCODE];        // 0.5*||e_k||^2
__device__ int    g_code[NTOK];
__device__ double g_partial[512];     // deterministic loss partials

// ---------------- f32x2 helpers (packed fp32 FMA, sm_100+) ----------------
__device__ __forceinline__ unsigned long long pack2(float a) {
    unsigned long long r;
    asm("mov.b64 %0, {%1, %1};" : "=l"(r) : "f"(a));
    return r;
}
__device__ __forceinline__ void fma2(unsigned long long& acc,
                                     unsigned long long a, unsigned long long b) {
    asm("fma.rn.f32x2 %0, %1, %2, %0;" : "+l"(acc) : "l"(a), "l"(b));
}
__device__ __forceinline__ void unpack2(unsigned long long v, float& lo, float& hi) {
    asm("mov.b64 {%0, %1}, %2;" : "=f"(lo), "=f"(hi) : "l"(v));
}
__device__ __forceinline__ float f4get(const float4& v, int q) {
    switch (q) { case 0: return v.x; case 1: return v.y; case 2: return v.z; default: return v.w; }
}

// ---------------- Kernel 1: transpose x (B,C,H,W) -> xT[token][c] ----------
__global__ void vq_transpose(const float* __restrict__ x) {
    __shared__ float tile[32][33];
    int c0 = blockIdx.x << 5, hw0 = blockIdx.y << 5, b = blockIdx.z;
    const float* xb = x + (size_t)b * (C_ * HW_);
#pragma unroll
    for (int k = 0; k < 4; ++k)
        tile[threadIdx.y + k * 8][threadIdx.x] =
            xb[(size_t)(c0 + threadIdx.y + k * 8) * HW_ + hw0 + threadIdx.x];
    __syncthreads();
#pragma unroll
    for (int k = 0; k < 4; ++k)
        g_xT[(size_t)(b * HW_ + hw0 + threadIdx.y + k * 8) * C_ + c0 + threadIdx.x] =
            tile[threadIdx.x][threadIdx.y + k * 8];
}

// ---------------- Kernel 2: half code norms ----------------
__global__ void vq_norms(const float* __restrict__ w) {
    int k = blockIdx.x * 256 + threadIdx.x;     // grid 32 x 256 = 8192 exactly
    const float4* r = (const float4*)(w + (size_t)k * C_);
    float s = 0.f;
#pragma unroll 8
    for (int i = 0; i < 64; ++i) {
        float4 v = r[i];
        s += v.x * v.x + v.y * v.y + v.z * v.z + v.w * v.w;
    }
    g_hn[k] = 0.5f * s;
}

// ---------------- Kernel 3: GEMM + argmax ----------------
// 128 CTAs x 256 threads. A-tile 128x256 persistent in smem; B in 64-code
// chunks (full C) with XOR swizzle; per-thread 8 tokens x 4 codes, f32x2 accum.
__global__ void __launch_bounds__(256, 1)
vq_argmax(const float* __restrict__ w) {
    extern __shared__ float sm[];
    float* As = sm;                  // [128][260] token-major, padded
    float* Bs = sm + 128 * 260;      // [256][64], col = code ^ (((c>>2)&7)<<2)

    int tid = threadIdx.x;
    int t0  = blockIdx.x << 7;

    // Load A tile (coalesced reads, conflict-free float4 stores)
#pragma unroll
    for (int p = 0; p < 32; ++p) {
        int pos = p * 256 + tid;
        int t = pos >> 6, cq = pos & 63;
        float4 v = *(const float4*)(g_xT + (size_t)(t0 + t) * C_ + (cq << 2));
        *(float4*)(As + t * 260 + (cq << 2)) = v;
    }

    int ty = tid >> 4, tx = tid & 15;
    int tyb = ty << 3;
    float best[8];
    int   bid[8];
#pragma unroll
    for (int i = 0; i < 8; ++i) { best[i] = -CUDART_INF_F; bid[i] = 0; }

    for (int n0 = 0; n0 < KCODE; n0 += 64) {
        __syncthreads();
        // Load 64 codes x 256 c into swizzled Bs (conflict-free scatter)
#pragma unroll
        for (int p = 0; p < 16; ++p) {
            int pos = p * 256 + tid;          // quad index 0..4095
            int cd  = (pos >> 3) & 63;
            int clo = pos & 7;
            int chi = pos >> 9;
            int cq  = (chi << 3) + clo;       // c>>2, 0..63
            float4 v = *(const float4*)(w + (size_t)(n0 + cd) * C_ + (cq << 2));
            int col = cd ^ (clo << 2);
            Bs[(cq * 4 + 0) * 64 + col] = v.x;
            Bs[(cq * 4 + 1) * 64 + col] = v.y;
            Bs[(cq * 4 + 2) * 64 + col] = v.z;
            Bs[(cq * 4 + 3) * 64 + col] = v.w;
        }
        __syncthreads();

        unsigned long long acc0[8], acc1[8];
#pragma unroll
        for (int i = 0; i < 8; ++i) { acc0[i] = 0ull; acc1[i] = 0ull; }

#pragma unroll 4
        for (int mm = 0; mm < 64; ++mm) {     // c = 4*mm .. 4*mm+3
            int colb = (tx << 2) ^ ((mm & 7) << 2);
            const float* brow = Bs + (mm << 2) * 64;
            float4 a4[8];
#pragma unroll
            for (int i = 0; i < 8; ++i)
                a4[i] = *(const float4*)(As + (tyb + i) * 260 + (mm << 2));
#pragma unroll
            for (int q = 0; q < 4; ++q) {
                unsigned long long b01 = *(const unsigned long long*)(brow + (q << 6) + colb);
                unsigned long long b23 = *(const unsigned long long*)(brow + (q << 6) + colb + 2);
#pragma unroll
                for (int i = 0; i < 8; ++i) {
                    unsigned long long aa = pack2(f4get(a4[i], q));
                    fma2(acc0[i], aa, b01);
                    fma2(acc1[i], aa, b23);
                }
            }
        }

        // score = dot - 0.5||e||^2 ; track running argmax (first-index ties)
        float4 h4 = *(const float4*)(g_hn + n0 + (tx << 2));
        int cb = n0 + (tx << 2);
#pragma unroll
        for (int i = 0; i < 8; ++i) {
            float s0, s1, s2, s3;
            unpack2(acc0[i], s0, s1);
            unpack2(acc1[i], s2, s3);
            s0 -= h4.x; s1 -= h4.y; s2 -= h4.z; s3 -= h4.w;
            if (s0 > best[i]) { best[i] = s0; bid[i] = cb; }
            if (s1 > best[i]) { best[i] = s1; bid[i] = cb + 1; }
            if (s2 > best[i]) { best[i] = s2; bid[i] = cb + 2; }
            if (s3 > best[i]) { best[i] = s3; bid[i] = cb + 3; }
        }
    }

    // Reduce across the 16 code-lanes (groups of 16 within each warp)
#pragma unroll
    for (int i = 0; i < 8; ++i) {
        float bv = best[i]; int idx = bid[i];
#pragma unroll
        for (int off = 8; off > 0; off >>= 1) {
            float ob = __shfl_down_sync(0xffffffffu, bv, off, 16);
            int   oi = __shfl_down_sync(0xffffffffu, idx, off, 16);
            if (ob > bv || (ob == bv && oi < idx)) { bv = ob; idx = oi; }
        }
        if (tx == 0) g_code[t0 + tyb + i] = idx;
    }
}

// ---------------- Kernel 4: gather x_q (B,C,H,W) + loss partials ----------
__global__ void vq_gather(const float* __restrict__ x, const float* __restrict__ w,
                          float* __restrict__ out) {
    int bx = blockIdx.x;                  // 0..511
    int b = bx >> 5, hw0 = (bx & 31) << 5;
    int tid = threadIdx.x;
    int hwl = tid & 31, cg = tid >> 5;
    int t = b * HW_ + hw0 + hwl;
    int k = g_code[t];
    const float* e  = w + (size_t)k * C_;
    const float* xb = x + (size_t)b * (C_ * HW_) + hw0 + hwl;
    float* ob = out + (size_t)b * (C_ * HW_) + hw0 + hwl;
    float ls = 0.f;
#pragma unroll
    for (int p = 0; p < 8; ++p) {
        int c0 = ((p << 3) + cg) << 2;
        float4 ev = *(const float4*)(e + c0);
#pragma unroll
        for (int j = 0; j < 4; ++j) {
            int c = c0 + j;
            float v  = f4get(ev, j);
            float xv = xb[(size_t)c * HW_];
            ob[(size_t)c * HW_] = v;
            float d = v - xv;
            ls += d * d;
        }
    }
#pragma unroll
    for (int off = 16; off > 0; off >>= 1)
        ls += __shfl_down_sync(0xffffffffu, ls, off);
    __shared__ float ws[8];
    if ((tid & 31) == 0) ws[tid >> 5] = ls;
    __syncthreads();
    if (tid == 0) {
        float s = 0.f;
#pragma unroll
        for (int i = 0; i < 8; ++i) s += ws[i];
        g_partial[bx] = (double)s;
    }
}

// ---------------- Kernel 5: finalize loss + code floats ----------------
__global__ void vq_finalize(float* __restrict__ out) {
    int idx = blockIdx.x * 256 + threadIdx.x;
    if (idx < NTOK) out[CODE_OFF + idx] = (float)g_code[idx];
    if (idx == 0) {
        double s = 0.0;
        for (int i = 0; i < 512; ++i) s += g_partial[i];
        out[LOSS_OFF] = (float)(1.25 * s / (double)XQ_SIZE);
    }
}

// ---------------- Launch ----------------
extern "C" void kernel_launch(void* const* d_in, const int* in_sizes, int n_in,
                              void* d_out, int out_size) {
    const float* x = (const float*)d_in[0];   // (16,256,32,32) fp32
    const float* w = (const float*)d_in[1];   // (8193,256) fp32
    float* out = (float*)d_out;

    const size_t SMEM = (size_t)(128 * 260 + 256 * 64) * sizeof(float); // 198656 B
    cudaFuncSetAttribute((const void*)vq_argmax,
                         cudaFuncAttributeMaxDynamicSharedMemorySize, (int)SMEM);

    vq_transpose<<<dim3(8, 32, 16), dim3(32, 8)>>>(x);
    vq_norms<<<32, 256>>>(w);
    vq_argmax<<<128, 256, SMEM>>>(w);
    vq_gather<<<512, 256>>>(x, w, out);
    vq_finalize<<<64, 256>>>(out);
}